// round 15
// baseline (speedup 1.0000x reference)
#include <cuda_runtime.h>
#include <cuda_bf16.h>
#include <cstdint>

// Problem constants
#define BB   2
#define NN   10000
#define EE   100000
#define FF   512
#define HH   512
#define MROWS (BB*NN)        // 20000 rows into the node GEMM
#define NTOT  (2*HH)         // 1024 cols: [W1 | W2]
#define NEDGE (BB*EE)        // 200000 directed edge slots
#define NSEG  (BB*NN)        // 20000 segments per direction

// ---------------- scratch (static device globals; no allocation) -------------
__device__ __nv_bfloat16  g_preb[(size_t)MROWS * NTOT];    // 41 MB: X@[W1|W2] bf16
__device__ __nv_bfloat16  g_Xb [(size_t)MROWS * FF];       // 20.5 MB bf16 X
__device__ __nv_bfloat16  g_Wb [(size_t)NTOT  * FF];       // 1 MB: [W1|W2]^T K-major
__device__ __nv_bfloat16  g_A1[(size_t)MROWS * HH];        // 20.5 MB
__device__ __nv_bfloat16  g_A2[(size_t)MROWS * HH];        // 20.5 MB
__device__ float          g_eij[NEDGE];
__device__ float          g_eji[NEDGE];
__device__ float          g_sums[2 * NSEG];                // [src sums | dst sums]

// ======================= PTX helpers (non-'a' safe) ===========================
__device__ __forceinline__ uint32_t smem_to_u32(const void* smem_ptr) {
    uint32_t addr;
    asm("{ .reg .u64 tmp; cvta.to.shared.u64 tmp, %1; cvt.u32.u64 %0, tmp; }"
        : "=r"(addr) : "l"(smem_ptr));
    return addr;
}

__device__ __forceinline__ void cp_async16(uint32_t dst, const void* src, int src_bytes) {
    asm volatile("cp.async.cg.shared.global [%0], [%1], 16, %2;"
        :: "r"(dst), "l"(src), "r"(src_bytes) : "memory");
}
#define CP_COMMIT() asm volatile("cp.async.commit_group;" ::: "memory")
#define CP_WAIT(n)  asm volatile("cp.async.wait_group %0;" :: "n"(n) : "memory")

__device__ __forceinline__ void ldmatrix_x4(
    uint32_t& r0, uint32_t& r1, uint32_t& r2, uint32_t& r3, uint32_t addr)
{
    asm volatile("ldmatrix.sync.aligned.m8n8.x4.shared.b16 {%0,%1,%2,%3}, [%4];"
        : "=r"(r0), "=r"(r1), "=r"(r2), "=r"(r3) : "r"(addr));
}

__device__ __forceinline__ void mma_bf16(
    float* c, uint32_t a0, uint32_t a1, uint32_t a2, uint32_t a3,
    uint32_t b0, uint32_t b1)
{
    asm volatile(
        "mma.sync.aligned.m16n8k16.row.col.f32.bf16.bf16.f32 "
        "{%0,%1,%2,%3}, {%4,%5,%6,%7}, {%8,%9}, {%0,%1,%2,%3};"
        : "+f"(c[0]), "+f"(c[1]), "+f"(c[2]), "+f"(c[3])
        : "r"(a0), "r"(a1), "r"(a2), "r"(a3), "r"(b0), "r"(b1));
}

__device__ __forceinline__ void bf8_to_f(uint4 u, float* f) {
    const __nv_bfloat162* p = (const __nv_bfloat162*)&u;
#pragma unroll
    for (int i = 0; i < 4; i++) {
        float2 t = __bfloat1622float2(p[i]);
        f[2 * i]     = t.x;
        f[2 * i + 1] = t.y;
    }
}

// ---------------- kernel P: fused prologue -----------------------------------
#define CONV_BLOCKS  ((int)(((size_t)MROWS * FF / 8 + 255) / 256))   // 5000
#define TRANS_BLOCKS ((FF / 32) * (NTOT / 32))                       // 512
#define ZERO_BLOCKS  ((2 * NSEG + 255) / 256)                        // 157

__global__ __launch_bounds__(256) void prologue_kernel(
    const float* __restrict__ X,
    const float* __restrict__ W1, const float* __restrict__ W2)
{
    int bid = blockIdx.x;
    int tid = threadIdx.x;

    if (bid < CONV_BLOCKS) {
        size_t i = ((size_t)bid * 256 + tid) * 8;
        if (i >= (size_t)MROWS * FF) return;
        float4 a = *(const float4*)(X + i);
        float4 b = *(const float4*)(X + i + 4);
        __nv_bfloat162 o0 = __float22bfloat162_rn(make_float2(a.x, a.y));
        __nv_bfloat162 o1 = __float22bfloat162_rn(make_float2(a.z, a.w));
        __nv_bfloat162 o2 = __float22bfloat162_rn(make_float2(b.x, b.y));
        __nv_bfloat162 o3 = __float22bfloat162_rn(make_float2(b.z, b.w));
        uint4 o;
        o.x = *(uint32_t*)&o0; o.y = *(uint32_t*)&o1;
        o.z = *(uint32_t*)&o2; o.w = *(uint32_t*)&o3;
        *(uint4*)(g_Xb + i) = o;
    } else if (bid < CONV_BLOCKS + TRANS_BLOCKS) {
        __shared__ float t[32][33];
        int tb  = bid - CONV_BLOCKS;
        int k0  = (tb % (FF / 32)) * 32;
        int n0g = (tb / (FF / 32)) * 32;
        const float* W = (n0g < HH) ? W1 : W2;
        int n0 = n0g & (HH - 1);
        int tx = tid & 31, ty = tid >> 5;   // (32, 8)
#pragma unroll
        for (int j = 0; j < 4; j++)
            t[ty + 8 * j][tx] = W[(size_t)(k0 + ty + 8 * j) * HH + n0 + tx];
        __syncthreads();
#pragma unroll
        for (int j = 0; j < 4; j++)
            g_Wb[(size_t)(n0g + ty + 8 * j) * FF + k0 + tx] =
                __float2bfloat16(t[tx][ty + 8 * j]);
    } else {
        int i = (bid - CONV_BLOCKS - TRANS_BLOCKS) * 256 + tid;
        if (i < 2 * NSEG) g_sums[i] = 0.0f;
    }
}

// ---------------- kernel 1: bf16 HMMA GEMM — 2-stage, 3 CTAs/SM ---------------
// CTA tile 128x128, BK=64, 2-stage cp.async pipeline, 8 warps = 4(m) x 2(n),
// warp tile 32x64. Single frag set (regs <= 85 for 3-CTA residency).
// Occupancy experiment: 24 warps/SM hide the shallower pipeline's latency.
#define BK    64
#define LDS_  ((BK) + 8)          // 72 bf16 per smem row (144B)
#define NSTG  2
#define TILE_BYTES   (128 * LDS_ * 2)
#define STAGE_BYTES  (2 * TILE_BYTES)
#define GEMM_SMEM    (NSTG * STAGE_BYTES)   // 73728 B -> 3 CTAs/SM

__global__ __launch_bounds__(256, 3) void gemm_mma_kernel()
{
    extern __shared__ __align__(16) char smem_raw[];
    const uint32_t sbase = smem_to_u32(smem_raw);

    const int tid  = threadIdx.x;
    const int wid  = tid >> 5;
    const int lane = tid & 31;

    const int m0 = blockIdx.y * 128;
    const int n0 = blockIdx.x * 128;

    const int warp_m = wid >> 1;
    const int warp_n = wid & 1;

    float acc[2][8][4];
#pragma unroll
    for (int i = 0; i < 2; i++)
#pragma unroll
        for (int j = 0; j < 8; j++)
#pragma unroll
            for (int q = 0; q < 4; q++) acc[i][j][q] = 0.0f;

    auto stageA = [&](int s) { return sbase + (uint32_t)s * STAGE_BYTES; };
    auto stageB = [&](int s) { return sbase + (uint32_t)s * STAGE_BYTES + TILE_BYTES; };

    auto load_tiles = [&](int it, int s) {
        int k0 = it * BK;
        uint32_t aA = stageA(s), aB = stageB(s);
#pragma unroll
        for (int j = 0; j < 4; j++) {
            int c   = tid + j * 256;
            int row = c >> 3;
            int sl  = c & 7;
            int gm  = m0 + row;
            uint32_t off = (uint32_t)(row * LDS_ + sl * 8) * 2;
            cp_async16(aA + off, g_Xb + (size_t)gm * FF + k0 + sl * 8,
                       (gm < MROWS) ? 16 : 0);
            cp_async16(aB + off, g_Wb + (size_t)(n0 + row) * FF + k0 + sl * 8, 16);
        }
        CP_COMMIT();
    };

    const int NIT = FF / BK;   // 8
    load_tiles(0, 0);

#pragma unroll 1
    for (int it = 0; it < NIT; ++it) {
        int s = it & 1;
        // Barrier at top: all warps finished computing iter it-1, whose buffer
        // ((it+1)&1) is the one the load below overwrites.
        __syncthreads();
        if (it + 1 < NIT) { load_tiles(it + 1, (it + 1) & 1); CP_WAIT(1); }
        else { CP_WAIT(0); }

        uint32_t aA = stageA(s), aB = stageB(s);
#pragma unroll
        for (int ks = 0; ks < BK; ks += 16) {
            uint32_t a[2][4];
#pragma unroll
            for (int tm = 0; tm < 2; tm++) {
                int r  = warp_m * 32 + tm * 16 + (lane & 15);
                int kk = ks + (lane >> 4) * 8;
                ldmatrix_x4(a[tm][0], a[tm][1], a[tm][2], a[tm][3],
                            aA + (uint32_t)(r * LDS_ + kk) * 2);
            }
            uint32_t b[8][2];
#pragma unroll
            for (int tp = 0; tp < 4; tp++) {
                int nrow = warp_n * 64 + tp * 16 + ((lane >> 4) * 8) + (lane & 7);
                int kk   = ks + (((lane >> 3) & 1) * 8);
                ldmatrix_x4(b[2*tp][0], b[2*tp][1], b[2*tp+1][0], b[2*tp+1][1],
                            aB + (uint32_t)(nrow * LDS_ + kk) * 2);
            }
#pragma unroll
            for (int tm = 0; tm < 2; tm++)
#pragma unroll
                for (int tn = 0; tn < 8; tn++)
                    mma_bf16(acc[tm][tn], a[tm][0], a[tm][1], a[tm][2], a[tm][3],
                             b[tn][0], b[tn][1]);
        }
    }

    // Epilogue: write bf16 to g_preb
    const int qrow = lane >> 2;
    const int qcol = (lane & 3) * 2;
#pragma unroll
    for (int tm = 0; tm < 2; tm++) {
        int mb = m0 + warp_m * 32 + tm * 16;
#pragma unroll
        for (int tn = 0; tn < 8; tn++) {
            int gcol = n0 + warp_n * 64 + tn * 8 + qcol;
            int r0 = mb + qrow;
            int r1 = mb + qrow + 8;
            __nv_bfloat162 p0 = __float22bfloat162_rn(
                make_float2(acc[tm][tn][0], acc[tm][tn][1]));
            __nv_bfloat162 p1 = __float22bfloat162_rn(
                make_float2(acc[tm][tn][2], acc[tm][tn][3]));
            if (r0 < MROWS)
                *(__nv_bfloat162*)(g_preb + (size_t)r0 * NTOT + gcol) = p0;
            if (r1 < MROWS)
                *(__nv_bfloat162*)(g_preb + (size_t)r1 * NTOT + gcol) = p1;
        }
    }
}

// ---------------- kernel 2: LayerNorm — one WARP per row-half ----------------
__global__ __launch_bounds__(256) void ln_kernel(
    const float* __restrict__ b1, const float* __restrict__ g1, const float* __restrict__ bb1,
    const float* __restrict__ b2, const float* __restrict__ g2, const float* __restrict__ bb2)
{
    int gw   = (blockIdx.x * 256 + threadIdx.x) >> 5;  // global half index
    int lane = threadIdx.x & 31;
    if (gw >= MROWS * 2) return;
    int row  = gw >> 1;
    int half = gw & 1;

    const __nv_bfloat16* p = g_preb + (size_t)row * NTOT + half * HH + lane * 16;
    const float* bv  = (half ? b2  : b1)  + lane * 16;
    const float* gv  = (half ? g2  : g1)  + lane * 16;
    const float* bbv = (half ? bb2 : bb1) + lane * 16;

    float v[16];
    bf8_to_f(*(const uint4*)(p),     v);
    bf8_to_f(*(const uint4*)(p + 8), v + 8);
#pragma unroll
    for (int q = 0; q < 4; q++) {
        float4 bq = *(const float4*)(bv + 4 * q);
        v[4*q]   += bq.x; v[4*q+1] += bq.y;
        v[4*q+2] += bq.z; v[4*q+3] += bq.w;
    }

    float s = 0.f, sq = 0.f;
#pragma unroll
    for (int j = 0; j < 16; j++) { s += v[j]; sq = fmaf(v[j], v[j], sq); }
#pragma unroll
    for (int o = 16; o; o >>= 1) {
        s  += __shfl_xor_sync(0xffffffffu, s,  o);
        sq += __shfl_xor_sync(0xffffffffu, sq, o);
    }

    float mu  = s * (1.0f / HH);
    float var = sq * (1.0f / HH) - mu * mu;
    float rs  = rsqrtf(var + 1e-5f);

    __nv_bfloat16* Aout = (half ? g_A2 : g_A1) + (size_t)row * HH + lane * 16;
    uint4 o0, o1;
    uint32_t* op = (uint32_t*)&o0;
#pragma unroll
    for (int q = 0; q < 4; q++) {
        float4 gq = *(const float4*)(gv + 4 * q);
        float4 bq = *(const float4*)(bbv + 4 * q);
        float e0 = (v[4*q]   - mu) * rs * gq.x + bq.x;
        float e1 = (v[4*q+1] - mu) * rs * gq.y + bq.y;
        float e2 = (v[4*q+2] - mu) * rs * gq.z + bq.z;
        float e3 = (v[4*q+3] - mu) * rs * gq.w + bq.w;
        __nv_bfloat162 pA = __float22bfloat162_rn(make_float2(e0, e1));
        __nv_bfloat162 pB = __float22bfloat162_rn(make_float2(e2, e3));
        if (q < 2) {
            op[2*q]   = *(uint32_t*)&pA;
            op[2*q+1] = *(uint32_t*)&pB;
        } else {
            ((uint32_t*)&o1)[2*(q-2)]   = *(uint32_t*)&pA;
            ((uint32_t*)&o1)[2*(q-2)+1] = *(uint32_t*)&pB;
        }
    }
    *(uint4*)(Aout)     = o0;
    *(uint4*)(Aout + 8) = o1;
}

// ---------------- edge math: all-bf16x2 packet (6 ops per 2 elems) ------------
__device__ __forceinline__ void edge_packet(
    uint32_t x1s, uint32_t x2s, uint32_t x1d, uint32_t x2d,
    uint32_t wb, uint32_t& acc1, uint32_t& acc2)
{
    uint32_t h1, h2;
    asm("add.rn.bf16x2 %0, %1, %2;" : "=r"(h1) : "r"(x1s), "r"(x2d));
    asm("add.rn.bf16x2 %0, %1, %2;" : "=r"(h2) : "r"(x1d), "r"(x2s));
    asm("max.bf16x2 %0, %1, %2;" : "=r"(h1) : "r"(h1), "r"(0u));
    asm("max.bf16x2 %0, %1, %2;" : "=r"(h2) : "r"(h2), "r"(0u));
    asm("fma.rn.bf16x2 %0, %1, %2, %3;" : "=r"(acc1) : "r"(h1), "r"(wb), "r"(acc1));
    asm("fma.rn.bf16x2 %0, %1, %2, %3;" : "=r"(acc2) : "r"(h2), "r"(wb), "r"(acc2));
}

__device__ __forceinline__ void drain_acc(uint32_t acc, float& s) {
    s += __uint_as_float(acc << 16) + __uint_as_float(acc & 0xffff0000u);
}

__device__ __forceinline__ uint32_t pack_bf2(float lo, float hi) {
    __nv_bfloat162 v = __float22bfloat162_rn(make_float2(lo, hi));
    return *(uint32_t*)&v;
}

// ---------------- kernel 3: 4 edges per warp, unroll 2 for MLP ---------------
#define EPW 4   // edges per warp (NEDGE divisible by EPW)

__global__ __launch_bounds__(256) void edge_kernel(
    const int* __restrict__ ei,
    const float* __restrict__ W3,
    const float* __restrict__ W4,
    const float* __restrict__ b4)
{
    int gw   = (blockIdx.x * 256 + threadIdx.x) >> 5;   // warp id
    int lane = threadIdx.x & 31;
    int ebase = gw * EPW;
    if (ebase >= NEDGE) return;

    // Hoisted: W3 slices as bf16x2 (8 packets) + scalars.
    const int off0 = lane * 8;
    const int off1 = (32 + lane) * 8;
    uint32_t wv[8];
    {
        float4 wa0 = *(const float4*)(W3 + off0);
        float4 wb0 = *(const float4*)(W3 + off0 + 4);
        float4 wa1 = *(const float4*)(W3 + off1);
        float4 wb1 = *(const float4*)(W3 + off1 + 4);
        wv[0] = pack_bf2(wa0.x, wa0.y); wv[1] = pack_bf2(wa0.z, wa0.w);
        wv[2] = pack_bf2(wb0.x, wb0.y); wv[3] = pack_bf2(wb0.z, wb0.w);
        wv[4] = pack_bf2(wa1.x, wa1.y); wv[5] = pack_bf2(wa1.z, wa1.w);
        wv[6] = pack_bf2(wb1.x, wb1.y); wv[7] = pack_bf2(wb1.z, wb1.w);
    }
    float w4 = W4[0], bb = b4[0];

#pragma unroll 2
    for (int q = 0; q < EPW; ++q) {
        int i = ebase + q;
        int b = i / EE;
        int e = i - b * EE;
        int src = ei[(size_t)b * 2 * EE + e];
        int dst = ei[(size_t)b * 2 * EE + EE + e];

        const __nv_bfloat16* a1s = g_A1 + ((size_t)b * NN + src) * HH;
        const __nv_bfloat16* a2s = g_A2 + ((size_t)b * NN + src) * HH;
        const __nv_bfloat16* a1d = g_A1 + ((size_t)b * NN + dst) * HH;
        const __nv_bfloat16* a2d = g_A2 + ((size_t)b * NN + dst) * HH;

        float s1 = 0.f, s2 = 0.f;
        {   // slice 0: packets 0-3, bf16 chain length 4, then drain
            uint4 U1s = *(const uint4*)(a1s + off0);
            uint4 U2s = *(const uint4*)(a2s + off0);
            uint4 U1d = *(const uint4*)(a1d + off0);
            uint4 U2d = *(const uint4*)(a2d + off0);
            uint32_t acc1 = 0u, acc2 = 0u;
            edge_packet(U1s.x, U2s.x, U1d.x, U2d.x, wv[0], acc1, acc2);
            edge_packet(U1s.y, U2s.y, U1d.y, U2d.y, wv[1], acc1, acc2);
            edge_packet(U1s.z, U2s.z, U1d.z, U2d.z, wv[2], acc1, acc2);
            edge_packet(U1s.w, U2s.w, U1d.w, U2d.w, wv[3], acc1, acc2);
            drain_acc(acc1, s1);
            drain_acc(acc2, s2);
        }
        {   // slice 1: packets 4-7
            uint4 U1s = *(const uint4*)(a1s + off1);
            uint4 U2s = *(const uint4*)(a2s + off1);
            uint4 U1d = *(const uint4*)(a1d + off1);
            uint4 U2d = *(const uint4*)(a2d + off1);
            uint32_t acc1 = 0u, acc2 = 0u;
            edge_packet(U1s.x, U2s.x, U1d.x, U2d.x, wv[4], acc1, acc2);
            edge_packet(U1s.y, U2s.y, U1d.y, U2d.y, wv[5], acc1, acc2);
            edge_packet(U1s.z, U2s.z, U1d.z, U2d.z, wv[6], acc1, acc2);
            edge_packet(U1s.w, U2s.w, U1d.w, U2d.w, wv[7], acc1, acc2);
            drain_acc(acc1, s1);
            drain_acc(acc2, s2);
        }

        // Combined reduction: lanes 0-15 reduce s1, lanes 16-31 reduce s2.
        float xa = __shfl_xor_sync(0xffffffffu, s1, 16);
        float xb = __shfl_xor_sync(0xffffffffu, s2, 16);
        float v  = (lane < 16) ? (s1 + xa) : (s2 + xb);
#pragma unroll
        for (int o = 8; o; o >>= 1)
            v += __shfl_xor_sync(0xffffffffu, v, o);
        float s2tot = __shfl_sync(0xffffffffu, v, 16);

        if (lane == 0) {
            float d   = v - s2tot;          // b3 cancels in Zij - Zji
            float vij = fmaxf(fmaf( d, w4, bb), 0.f);
            float vji = fmaxf(fmaf(-d, w4, bb), 0.f);
            float pi = expf(vij);           // max-subtraction removable: exact ratio
            float pj = expf(vji);
            g_eij[i] = pi;
            g_eji[i] = pj;
            atomicAdd(&g_sums[b * NN + src], pi);
            atomicAdd(&g_sums[NSEG + b * NN + dst], pj);
        }
    }
}

// ---------------- kernel 4: normalize + write output -------------------------
__global__ __launch_bounds__(256) void norm_kernel(
    const int* __restrict__ ei,
    float* __restrict__ out)
{
    int i = blockIdx.x * 256 + threadIdx.x;
    if (i >= NEDGE) return;
    int b = i / EE;
    int e = i - b * EE;
    int src = ei[(size_t)b * 2 * EE + e];
    int dst = ei[(size_t)b * 2 * EE + EE + e];
    out[i]         = g_eij[i] / g_sums[b * NN + src];
    out[NEDGE + i] = g_eji[i] / g_sums[NSEG + b * NN + dst];
}

// ---------------- launcher ---------------------------------------------------
extern "C" void kernel_launch(void* const* d_in, const int* in_sizes, int n_in,
                              void* d_out, int out_size)
{
    int idx = 0;
    const float* X  = (const float*)d_in[idx++];   // node_features
    const int*   EI = (const int*)  d_in[idx++];   // edge_index
    if (idx < n_in && in_sizes[idx] == 1) idx++;   // num_nodes scalar (if present)
    const float* W1  = (const float*)d_in[idx++];
    const float* b1  = (const float*)d_in[idx++];
    const float* g1  = (const float*)d_in[idx++];
    const float* bb1 = (const float*)d_in[idx++];
    const float* W2  = (const float*)d_in[idx++];
    const float* b2  = (const float*)d_in[idx++];
    const float* g2  = (const float*)d_in[idx++];
    const float* bb2 = (const float*)d_in[idx++];
    const float* W3  = (const float*)d_in[idx++];
    idx++;                                          // b3 (cancels)
    const float* W4  = (const float*)d_in[idx++];
    const float* b4  = (const float*)d_in[idx++];

    float* out = (float*)d_out;

    prologue_kernel<<<CONV_BLOCKS + TRANS_BLOCKS + ZERO_BLOCKS, 256>>>(X, W1, W2);

    cudaFuncSetAttribute(gemm_mma_kernel,
                         cudaFuncAttributeMaxDynamicSharedMemorySize, GEMM_SMEM);
    dim3 ggrid(NTOT / 128, (MROWS + 127) / 128);
    gemm_mma_kernel<<<ggrid, 256, GEMM_SMEM>>>();

    int ln_warps  = MROWS * 2;                      // 40000 row-halves
    int ln_blocks = (ln_warps * 32 + 255) / 256;    // 5000
    ln_kernel<<<ln_blocks, 256>>>(b1, g1, bb1, b2, g2, bb2);

    int edge_warps  = NEDGE / EPW;                  // 50000
    int edge_blocks = (edge_warps * 32 + 255) / 256;
    edge_kernel<<<edge_blocks, 256>>>(EI, W3, W4, b4);

    norm_kernel<<<(NEDGE + 255) / 256, 256>>>(EI, out);
}

// round 16
// speedup vs baseline: 1.2198x; 1.2198x over previous
#include <cuda_runtime.h>
#include <cuda_bf16.h>
#include <cstdint>

// Problem constants
#define BB   2
#define NN   10000
#define EE   100000
#define FF   512
#define HH   512
#define MROWS (BB*NN)        // 20000 rows into the node GEMM
#define NTOT  (2*HH)         // 1024 cols: [W1 | W2]
#define NEDGE (BB*EE)        // 200000 directed edge slots
#define NSEG  (BB*NN)        // 20000 segments per direction

// ---------------- scratch (static device globals; no allocation) -------------
__device__ __nv_bfloat16  g_preb[(size_t)MROWS * NTOT];    // 41 MB: X@[W1|W2] bf16
__device__ __nv_bfloat16  g_Xb [(size_t)MROWS * FF];       // 20.5 MB bf16 X
__device__ __nv_bfloat16  g_Wb [(size_t)NTOT  * FF];       // 1 MB: [W1|W2]^T K-major
__device__ __nv_bfloat16  g_A1[(size_t)MROWS * HH];        // 20.5 MB
__device__ __nv_bfloat16  g_A2[(size_t)MROWS * HH];        // 20.5 MB
__device__ float          g_eij[NEDGE];
__device__ float          g_eji[NEDGE];
__device__ float          g_sums[2 * NSEG];                // [src sums | dst sums]

// ======================= PTX helpers (non-'a' safe) ===========================
__device__ __forceinline__ uint32_t smem_to_u32(const void* smem_ptr) {
    uint32_t addr;
    asm("{ .reg .u64 tmp; cvta.to.shared.u64 tmp, %1; cvt.u32.u64 %0, tmp; }"
        : "=r"(addr) : "l"(smem_ptr));
    return addr;
}

__device__ __forceinline__ void cp_async16(uint32_t dst, const void* src, int src_bytes) {
    asm volatile("cp.async.cg.shared.global [%0], [%1], 16, %2;"
        :: "r"(dst), "l"(src), "r"(src_bytes) : "memory");
}
#define CP_COMMIT() asm volatile("cp.async.commit_group;" ::: "memory")
#define CP_WAIT(n)  asm volatile("cp.async.wait_group %0;" :: "n"(n) : "memory")

__device__ __forceinline__ void ldmatrix_x4(
    uint32_t& r0, uint32_t& r1, uint32_t& r2, uint32_t& r3, uint32_t addr)
{
    asm volatile("ldmatrix.sync.aligned.m8n8.x4.shared.b16 {%0,%1,%2,%3}, [%4];"
        : "=r"(r0), "=r"(r1), "=r"(r2), "=r"(r3) : "r"(addr));
}

__device__ __forceinline__ void mma_bf16(
    float* c, uint32_t a0, uint32_t a1, uint32_t a2, uint32_t a3,
    uint32_t b0, uint32_t b1)
{
    asm volatile(
        "mma.sync.aligned.m16n8k16.row.col.f32.bf16.bf16.f32 "
        "{%0,%1,%2,%3}, {%4,%5,%6,%7}, {%8,%9}, {%0,%1,%2,%3};"
        : "+f"(c[0]), "+f"(c[1]), "+f"(c[2]), "+f"(c[3])
        : "r"(a0), "r"(a1), "r"(a2), "r"(a3), "r"(b0), "r"(b1));
}

__device__ __forceinline__ void bf8_to_f(uint4 u, float* f) {
    const __nv_bfloat162* p = (const __nv_bfloat162*)&u;
#pragma unroll
    for (int i = 0; i < 4; i++) {
        float2 t = __bfloat1622float2(p[i]);
        f[2 * i]     = t.x;
        f[2 * i + 1] = t.y;
    }
}

// ---------------- kernel P: fused prologue -----------------------------------
#define CONV_BLOCKS  ((int)(((size_t)MROWS * FF / 8 + 255) / 256))   // 5000
#define TRANS_BLOCKS ((FF / 32) * (NTOT / 32))                       // 512
#define ZERO_BLOCKS  ((2 * NSEG + 255) / 256)                        // 157

__global__ __launch_bounds__(256) void prologue_kernel(
    const float* __restrict__ X,
    const float* __restrict__ W1, const float* __restrict__ W2)
{
    int bid = blockIdx.x;
    int tid = threadIdx.x;

    if (bid < CONV_BLOCKS) {
        size_t i = ((size_t)bid * 256 + tid) * 8;
        if (i >= (size_t)MROWS * FF) return;
        float4 a = *(const float4*)(X + i);
        float4 b = *(const float4*)(X + i + 4);
        __nv_bfloat162 o0 = __float22bfloat162_rn(make_float2(a.x, a.y));
        __nv_bfloat162 o1 = __float22bfloat162_rn(make_float2(a.z, a.w));
        __nv_bfloat162 o2 = __float22bfloat162_rn(make_float2(b.x, b.y));
        __nv_bfloat162 o3 = __float22bfloat162_rn(make_float2(b.z, b.w));
        uint4 o;
        o.x = *(uint32_t*)&o0; o.y = *(uint32_t*)&o1;
        o.z = *(uint32_t*)&o2; o.w = *(uint32_t*)&o3;
        *(uint4*)(g_Xb + i) = o;
    } else if (bid < CONV_BLOCKS + TRANS_BLOCKS) {
        __shared__ float t[32][33];
        int tb  = bid - CONV_BLOCKS;
        int k0  = (tb % (FF / 32)) * 32;
        int n0g = (tb / (FF / 32)) * 32;
        const float* W = (n0g < HH) ? W1 : W2;
        int n0 = n0g & (HH - 1);
        int tx = tid & 31, ty = tid >> 5;   // (32, 8)
#pragma unroll
        for (int j = 0; j < 4; j++)
            t[ty + 8 * j][tx] = W[(size_t)(k0 + ty + 8 * j) * HH + n0 + tx];
        __syncthreads();
#pragma unroll
        for (int j = 0; j < 4; j++)
            g_Wb[(size_t)(n0g + ty + 8 * j) * FF + k0 + tx] =
                __float2bfloat16(t[tx][ty + 8 * j]);
    } else {
        int i = (bid - CONV_BLOCKS - TRANS_BLOCKS) * 256 + tid;
        if (i < 2 * NSEG) g_sums[i] = 0.0f;
    }
}

// ---------------- kernel 1: bf16 HMMA GEMM + fragment double-buffering --------
// FROZEN: round-12/14 champion config. 3-stage cp.async, 2 CTAs/SM, CTA tile
// 128x128, BK=64, 8 warps = 4(m) x 2(n), warp tile 32x64, frag ping-pong.
#define BK    64
#define LDS_  ((BK) + 8)          // 72 bf16 per smem row (144B)
#define NSTG  3
#define TILE_BYTES   (128 * LDS_ * 2)
#define STAGE_BYTES  (2 * TILE_BYTES)
#define GEMM_SMEM    (NSTG * STAGE_BYTES)

__global__ __launch_bounds__(256, 2) void gemm_mma_kernel()
{
    extern __shared__ __align__(16) char smem_raw[];
    const uint32_t sbase = smem_to_u32(smem_raw);

    const int tid  = threadIdx.x;
    const int wid  = tid >> 5;
    const int lane = tid & 31;

    const int m0 = blockIdx.y * 128;
    const int n0 = blockIdx.x * 128;

    const int warp_m = wid >> 1;
    const int warp_n = wid & 1;

    float acc[2][8][4];
#pragma unroll
    for (int i = 0; i < 2; i++)
#pragma unroll
        for (int j = 0; j < 8; j++)
#pragma unroll
            for (int q = 0; q < 4; q++) acc[i][j][q] = 0.0f;

    auto stageA = [&](int s) { return sbase + (uint32_t)s * STAGE_BYTES; };
    auto stageB = [&](int s) { return sbase + (uint32_t)s * STAGE_BYTES + TILE_BYTES; };

    auto load_tiles = [&](int it, int s) {
        int k0 = it * BK;
        uint32_t aA = stageA(s), aB = stageB(s);
#pragma unroll
        for (int j = 0; j < 4; j++) {
            int c   = tid + j * 256;
            int row = c >> 3;
            int sl  = c & 7;
            int gm  = m0 + row;
            uint32_t off = (uint32_t)(row * LDS_ + sl * 8) * 2;
            cp_async16(aA + off, g_Xb + (size_t)gm * FF + k0 + sl * 8,
                       (gm < MROWS) ? 16 : 0);
            cp_async16(aB + off, g_Wb + (size_t)(n0 + row) * FF + k0 + sl * 8, 16);
        }
        CP_COMMIT();
    };

    auto load_frags = [&](uint32_t aA, uint32_t aB, int ks,
                          uint32_t a[2][4], uint32_t b[8][2]) {
#pragma unroll
        for (int tm = 0; tm < 2; tm++) {
            int r  = warp_m * 32 + tm * 16 + (lane & 15);
            int kk = ks + (lane >> 4) * 8;
            ldmatrix_x4(a[tm][0], a[tm][1], a[tm][2], a[tm][3],
                        aA + (uint32_t)(r * LDS_ + kk) * 2);
        }
#pragma unroll
        for (int tp = 0; tp < 4; tp++) {
            int nrow = warp_n * 64 + tp * 16 + ((lane >> 4) * 8) + (lane & 7);
            int kk   = ks + (((lane >> 3) & 1) * 8);
            ldmatrix_x4(b[2*tp][0], b[2*tp][1], b[2*tp+1][0], b[2*tp+1][1],
                        aB + (uint32_t)(nrow * LDS_ + kk) * 2);
        }
    };

    const int NIT = FF / BK;   // 8
    load_tiles(0, 0);
    load_tiles(1, 1);

    uint32_t afr[2][2][4], bfr[2][8][2];

#pragma unroll 1
    for (int it = 0; it < NIT; ++it) {
        int s = it % NSTG;
        __syncthreads();
        if (it + 2 < NIT) { load_tiles(it + 2, (it + 2) % NSTG); CP_WAIT(2); }
        else if (it + 1 < NIT) { CP_WAIT(1); }
        else { CP_WAIT(0); }

        uint32_t aA = stageA(s), aB = stageB(s);

        load_frags(aA, aB, 0, afr[0], bfr[0]);
#pragma unroll
        for (int kg = 0; kg < BK / 16; ++kg) {
            int cur = kg & 1, nxt = cur ^ 1;
            if (kg + 1 < BK / 16)
                load_frags(aA, aB, (kg + 1) * 16, afr[nxt], bfr[nxt]);
#pragma unroll
            for (int tm = 0; tm < 2; tm++)
#pragma unroll
                for (int tn = 0; tn < 8; tn++)
                    mma_bf16(acc[tm][tn],
                             afr[cur][tm][0], afr[cur][tm][1],
                             afr[cur][tm][2], afr[cur][tm][3],
                             bfr[cur][tn][0], bfr[cur][tn][1]);
        }
    }

    const int qrow = lane >> 2;
    const int qcol = (lane & 3) * 2;
#pragma unroll
    for (int tm = 0; tm < 2; tm++) {
        int mb = m0 + warp_m * 32 + tm * 16;
#pragma unroll
        for (int tn = 0; tn < 8; tn++) {
            int gcol = n0 + warp_n * 64 + tn * 8 + qcol;
            int r0 = mb + qrow;
            int r1 = mb + qrow + 8;
            __nv_bfloat162 p0 = __float22bfloat162_rn(
                make_float2(acc[tm][tn][0], acc[tm][tn][1]));
            __nv_bfloat162 p1 = __float22bfloat162_rn(
                make_float2(acc[tm][tn][2], acc[tm][tn][3]));
            if (r0 < MROWS)
                *(__nv_bfloat162*)(g_preb + (size_t)r0 * NTOT + gcol) = p0;
            if (r1 < MROWS)
                *(__nv_bfloat162*)(g_preb + (size_t)r1 * NTOT + gcol) = p1;
        }
    }
}

// ---------------- kernel 2: LayerNorm — one WARP per row-half ----------------
__global__ __launch_bounds__(256) void ln_kernel(
    const float* __restrict__ b1, const float* __restrict__ g1, const float* __restrict__ bb1,
    const float* __restrict__ b2, const float* __restrict__ g2, const float* __restrict__ bb2)
{
    int gw   = (blockIdx.x * 256 + threadIdx.x) >> 5;  // global half index
    int lane = threadIdx.x & 31;
    if (gw >= MROWS * 2) return;
    int row  = gw >> 1;
    int half = gw & 1;

    const __nv_bfloat16* p = g_preb + (size_t)row * NTOT + half * HH + lane * 16;
    const float* bv  = (half ? b2  : b1)  + lane * 16;
    const float* gv  = (half ? g2  : g1)  + lane * 16;
    const float* bbv = (half ? bb2 : bb1) + lane * 16;

    float v[16];
    bf8_to_f(*(const uint4*)(p),     v);
    bf8_to_f(*(const uint4*)(p + 8), v + 8);
#pragma unroll
    for (int q = 0; q < 4; q++) {
        float4 bq = *(const float4*)(bv + 4 * q);
        v[4*q]   += bq.x; v[4*q+1] += bq.y;
        v[4*q+2] += bq.z; v[4*q+3] += bq.w;
    }

    float s = 0.f, sq = 0.f;
#pragma unroll
    for (int j = 0; j < 16; j++) { s += v[j]; sq = fmaf(v[j], v[j], sq); }
#pragma unroll
    for (int o = 16; o; o >>= 1) {
        s  += __shfl_xor_sync(0xffffffffu, s,  o);
        sq += __shfl_xor_sync(0xffffffffu, sq, o);
    }

    float mu  = s * (1.0f / HH);
    float var = sq * (1.0f / HH) - mu * mu;
    float rs  = rsqrtf(var + 1e-5f);

    __nv_bfloat16* Aout = (half ? g_A2 : g_A1) + (size_t)row * HH + lane * 16;
    uint4 o0, o1;
    uint32_t* op = (uint32_t*)&o0;
#pragma unroll
    for (int q = 0; q < 4; q++) {
        float4 gq = *(const float4*)(gv + 4 * q);
        float4 bq = *(const float4*)(bbv + 4 * q);
        float e0 = (v[4*q]   - mu) * rs * gq.x + bq.x;
        float e1 = (v[4*q+1] - mu) * rs * gq.y + bq.y;
        float e2 = (v[4*q+2] - mu) * rs * gq.z + bq.z;
        float e3 = (v[4*q+3] - mu) * rs * gq.w + bq.w;
        __nv_bfloat162 pA = __float22bfloat162_rn(make_float2(e0, e1));
        __nv_bfloat162 pB = __float22bfloat162_rn(make_float2(e2, e3));
        if (q < 2) {
            op[2*q]   = *(uint32_t*)&pA;
            op[2*q+1] = *(uint32_t*)&pB;
        } else {
            ((uint32_t*)&o1)[2*(q-2)]   = *(uint32_t*)&pA;
            ((uint32_t*)&o1)[2*(q-2)+1] = *(uint32_t*)&pB;
        }
    }
    *(uint4*)(Aout)     = o0;
    *(uint4*)(Aout + 8) = o1;
}

// ---------------- edge math: all-bf16x2 packet (6 ops per 2 elems) ------------
__device__ __forceinline__ void edge_packet(
    uint32_t x1s, uint32_t x2s, uint32_t x1d, uint32_t x2d,
    uint32_t wb, uint32_t& acc1, uint32_t& acc2)
{
    uint32_t h1, h2;
    asm("add.rn.bf16x2 %0, %1, %2;" : "=r"(h1) : "r"(x1s), "r"(x2d));
    asm("add.rn.bf16x2 %0, %1, %2;" : "=r"(h2) : "r"(x1d), "r"(x2s));
    asm("max.bf16x2 %0, %1, %2;" : "=r"(h1) : "r"(h1), "r"(0u));
    asm("max.bf16x2 %0, %1, %2;" : "=r"(h2) : "r"(h2), "r"(0u));
    asm("fma.rn.bf16x2 %0, %1, %2, %3;" : "=r"(acc1) : "r"(h1), "r"(wb), "r"(acc1));
    asm("fma.rn.bf16x2 %0, %1, %2, %3;" : "=r"(acc2) : "r"(h2), "r"(wb), "r"(acc2));
}

__device__ __forceinline__ void drain_acc(uint32_t acc, float& s) {
    s += __uint_as_float(acc << 16) + __uint_as_float(acc & 0xffff0000u);
}

__device__ __forceinline__ uint32_t pack_bf2(float lo, float hi) {
    __nv_bfloat162 v = __float22bfloat162_rn(make_float2(lo, hi));
    return *(uint32_t*)&v;
}

// ---------------- kernel 3: 8 edges per warp, unroll 2 for MLP ---------------
#define EPW 8   // edges per warp (NEDGE divisible by EPW)

__global__ __launch_bounds__(256) void edge_kernel(
    const int* __restrict__ ei,
    const float* __restrict__ W3,
    const float* __restrict__ W4,
    const float* __restrict__ b4)
{
    int gw   = (blockIdx.x * 256 + threadIdx.x) >> 5;   // warp id
    int lane = threadIdx.x & 31;
    int ebase = gw * EPW;
    if (ebase >= NEDGE) return;

    // Hoisted: W3 slices as bf16x2 (8 packets) + scalars — amortized over EPW edges.
    const int off0 = lane * 8;
    const int off1 = (32 + lane) * 8;
    uint32_t wv[8];
    {
        float4 wa0 = *(const float4*)(W3 + off0);
        float4 wb0 = *(const float4*)(W3 + off0 + 4);
        float4 wa1 = *(const float4*)(W3 + off1);
        float4 wb1 = *(const float4*)(W3 + off1 + 4);
        wv[0] = pack_bf2(wa0.x, wa0.y); wv[1] = pack_bf2(wa0.z, wa0.w);
        wv[2] = pack_bf2(wb0.x, wb0.y); wv[3] = pack_bf2(wb0.z, wb0.w);
        wv[4] = pack_bf2(wa1.x, wa1.y); wv[5] = pack_bf2(wa1.z, wa1.w);
        wv[6] = pack_bf2(wb1.x, wb1.y); wv[7] = pack_bf2(wb1.z, wb1.w);
    }
    float w4 = W4[0], bb = b4[0];

#pragma unroll 2
    for (int q = 0; q < EPW; ++q) {
        int i = ebase + q;
        int b = i / EE;
        int e = i - b * EE;
        int src = ei[(size_t)b * 2 * EE + e];
        int dst = ei[(size_t)b * 2 * EE + EE + e];

        const __nv_bfloat16* a1s = g_A1 + ((size_t)b * NN + src) * HH;
        const __nv_bfloat16* a2s = g_A2 + ((size_t)b * NN + src) * HH;
        const __nv_bfloat16* a1d = g_A1 + ((size_t)b * NN + dst) * HH;
        const __nv_bfloat16* a2d = g_A2 + ((size_t)b * NN + dst) * HH;

        float s1 = 0.f, s2 = 0.f;
        {   // slice 0: packets 0-3, bf16 chain length 4, then drain
            uint4 U1s = *(const uint4*)(a1s + off0);
            uint4 U2s = *(const uint4*)(a2s + off0);
            uint4 U1d = *(const uint4*)(a1d + off0);
            uint4 U2d = *(const uint4*)(a2d + off0);
            uint32_t acc1 = 0u, acc2 = 0u;
            edge_packet(U1s.x, U2s.x, U1d.x, U2d.x, wv[0], acc1, acc2);
            edge_packet(U1s.y, U2s.y, U1d.y, U2d.y, wv[1], acc1, acc2);
            edge_packet(U1s.z, U2s.z, U1d.z, U2d.z, wv[2], acc1, acc2);
            edge_packet(U1s.w, U2s.w, U1d.w, U2d.w, wv[3], acc1, acc2);
            drain_acc(acc1, s1);
            drain_acc(acc2, s2);
        }
        {   // slice 1: packets 4-7
            uint4 U1s = *(const uint4*)(a1s + off1);
            uint4 U2s = *(const uint4*)(a2s + off1);
            uint4 U1d = *(const uint4*)(a1d + off1);
            uint4 U2d = *(const uint4*)(a2d + off1);
            uint32_t acc1 = 0u, acc2 = 0u;
            edge_packet(U1s.x, U2s.x, U1d.x, U2d.x, wv[4], acc1, acc2);
            edge_packet(U1s.y, U2s.y, U1d.y, U2d.y, wv[5], acc1, acc2);
            edge_packet(U1s.z, U2s.z, U1d.z, U2d.z, wv[6], acc1, acc2);
            edge_packet(U1s.w, U2s.w, U1d.w, U2d.w, wv[7], acc1, acc2);
            drain_acc(acc1, s1);
            drain_acc(acc2, s2);
        }

        // Combined reduction: lanes 0-15 reduce s1, lanes 16-31 reduce s2.
        float xa = __shfl_xor_sync(0xffffffffu, s1, 16);
        float xb = __shfl_xor_sync(0xffffffffu, s2, 16);
        float v  = (lane < 16) ? (s1 + xa) : (s2 + xb);
#pragma unroll
        for (int o = 8; o; o >>= 1)
            v += __shfl_xor_sync(0xffffffffu, v, o);
        float s2tot = __shfl_sync(0xffffffffu, v, 16);

        if (lane == 0) {
            float d   = v - s2tot;          // b3 cancels in Zij - Zji
            float vij = fmaxf(fmaf( d, w4, bb), 0.f);
            float vji = fmaxf(fmaf(-d, w4, bb), 0.f);
            float pi = expf(vij);           // max-subtraction removable: exact ratio
            float pj = expf(vji);
            g_eij[i] = pi;
            g_eji[i] = pj;
            atomicAdd(&g_sums[b * NN + src], pi);
            atomicAdd(&g_sums[NSEG + b * NN + dst], pj);
        }
    }
}

// ---------------- kernel 4: normalize + write output -------------------------
__global__ __launch_bounds__(256) void norm_kernel(
    const int* __restrict__ ei,
    float* __restrict__ out)
{
    int i = blockIdx.x * 256 + threadIdx.x;
    if (i >= NEDGE) return;
    int b = i / EE;
    int e = i - b * EE;
    int src = ei[(size_t)b * 2 * EE + e];
    int dst = ei[(size_t)b * 2 * EE + EE + e];
    out[i]         = g_eij[i] / g_sums[b * NN + src];
    out[NEDGE + i] = g_eji[i] / g_sums[NSEG + b * NN + dst];
}

// ---------------- launcher ---------------------------------------------------
extern "C" void kernel_launch(void* const* d_in, const int* in_sizes, int n_in,
                              void* d_out, int out_size)
{
    int idx = 0;
    const float* X  = (const float*)d_in[idx++];   // node_features
    const int*   EI = (const int*)  d_in[idx++];   // edge_index
    if (idx < n_in && in_sizes[idx] == 1) idx++;   // num_nodes scalar (if present)
    const float* W1  = (const float*)d_in[idx++];
    const float* b1  = (const float*)d_in[idx++];
    const float* g1  = (const float*)d_in[idx++];
    const float* bb1 = (const float*)d_in[idx++];
    const float* W2  = (const float*)d_in[idx++];
    const float* b2  = (const float*)d_in[idx++];
    const float* g2  = (const float*)d_in[idx++];
    const float* bb2 = (const float*)d_in[idx++];
    const float* W3  = (const float*)d_in[idx++];
    idx++;                                          // b3 (cancels)
    const float* W4  = (const float*)d_in[idx++];
    const float* b4  = (const float*)d_in[idx++];

    float* out = (float*)d_out;

    prologue_kernel<<<CONV_BLOCKS + TRANS_BLOCKS + ZERO_BLOCKS, 256>>>(X, W1, W2);

    cudaFuncSetAttribute(gemm_mma_kernel,
                         cudaFuncAttributeMaxDynamicSharedMemorySize, GEMM_SMEM);
    dim3 ggrid(NTOT / 128, (MROWS + 127) / 128);
    gemm_mma_kernel<<<ggrid, 256, GEMM_SMEM>>>();

    int ln_warps  = MROWS * 2;                      // 40000 row-halves
    int ln_blocks = (ln_warps * 32 + 255) / 256;    // 5000
    ln_kernel<<<ln_blocks, 256>>>(b1, g1, bb1, b2, g2, bb2);

    int edge_warps  = NEDGE / EPW;                  // 25000
    int edge_blocks = (edge_warps * 32 + 255) / 256;
    edge_kernel<<<edge_blocks, 256>>>(EI, W3, W4, b4);

    norm_kernel<<<(NEDGE + 255) / 256, 256>>>(EI, out);
}